// round 3
// baseline (speedup 1.0000x reference)
#include <cuda_runtime.h>

// CostVolume: out[bh, w, d] = (1/64) * sum_c L[bh,w,c] * R[bh, w-d-1, c],
// zero where w-d-1 < 0.   W=512, C=64, D=64, BH derived.
//
// Block = 128-w tile x 64 d, 64 threads, each an 8w x 16d register tile
// (fp32x2 packed FMA).  C split in two 32-channel phases (42KB smem).
// Conflict-free without swizzle: pitches 132/196 (pitch/4 == 1 mod 8) +
// group-of-8 channel rotation cp = (ci & ~7) | ((ci + ty%8) & 7).

typedef unsigned long long ull;

namespace {
constexpr int Wd    = 512;
constexpr int Cd    = 64;
constexpr int Dd    = 64;
constexpr int WT    = 128;          // w-tile per block
constexpr int RROWS = WT + 64;      // 192 R rows (left halo 64)
constexpr int CP    = 32;           // channels per phase
constexpr int SLP   = WT + 4;       // 132: /4 = 33 == 1 (mod 8)
constexpr int SRP   = RROWS + 4;    // 196: /4 = 49 == 1 (mod 8)
}

// pair {hi(x), lo(y)} -> the "odd-offset" float pair
__device__ __forceinline__ ull mid2(ull x, ull y) {
    ull r;
    asm("{\n\t.reg .b32 a,b,c,d;\n\t"
        "mov.b64 {a,b}, %1;\n\t"
        "mov.b64 {c,d}, %2;\n\t"
        "mov.b64 %0, {b,c};\n\t}"
        : "=l"(r) : "l"(x), "l"(y));
    return r;
}
__device__ __forceinline__ void ffma2(ull& d, ull a, ull b) {
    asm("fma.rn.f32x2 %0, %1, %2, %0;" : "+l"(d) : "l"(a), "l"(b));
}
__device__ __forceinline__ void unpack2(ull v, float& lo, float& hi) {
    asm("mov.b64 {%0, %1}, %2;" : "=f"(lo), "=f"(hi) : "l"(v));
}

__global__ __launch_bounds__(64, 4)
void cost_volume_kernel(const float* __restrict__ left,
                        const float* __restrict__ right,
                        float* __restrict__ out) {
    __shared__ float Ls[CP * SLP];   // [c][w_local]
    __shared__ float Rs[CP * SRP];   // [c][src_local]

    const int tid = threadIdx.x;
    const int w0  = blockIdx.x * WT;
    const int bh  = blockIdx.y;
    const float* lrow = left  + (size_t)bh * Wd * Cd;
    const float* rrow = right + (size_t)bh * Wd * Cd;

    // compute mapping: ty in LOW bits (drives conflict-freedom), tx in high
    const int tx = tid >> 4;            // 0..3 : d-group, d = 16*tx + j
    const int ty = tid & 15;            // 0..15: w-group, w_local = 8*ty + i
    const int t  = ty & 7;
    const int lb = ty * 8;
    const int xb = 8 * ty - 16 * tx + 48;   // R window base, in [0,168]

    // per-thread rotated row offsets (group-of-8 rotation)
    int ro_l[8], ro_r[8];
#pragma unroll
    for (int k = 0; k < 8; k++) {
        const int rk = (k + t) & 7;
        ro_l[k] = rk * SLP;
        ro_r[k] = rk * SRP;
    }

    // fill mapping
    const int fc = tid & 31;            // channel within phase
    const int fg = tid >> 5;            // 0..1

    ull p[4][16];                        // acc pairs: {acc[2ii][j], acc[2ii+1][j]}
#pragma unroll
    for (int ii = 0; ii < 4; ii++)
#pragma unroll
        for (int j = 0; j < 16; j++) p[ii][j] = 0ull;

    for (int ph = 0; ph < 2; ph++) {
        const int cb = ph * CP;
        if (ph) __syncthreads();

        // ---- fill: gmem [row][c] -> smem [c][row], no swizzle needed ----
        for (int r0 = 4 * fg; r0 < WT; r0 += 8) {
            const float* src = lrow + (size_t)(w0 + r0) * Cd + cb + fc;
            float4 v;
            v.x = src[0]; v.y = src[Cd]; v.z = src[2 * Cd]; v.w = src[3 * Cd];
            *(float4*)&Ls[fc * SLP + r0] = v;
        }
        for (int r0 = 4 * fg; r0 < RROWS; r0 += 8) {
            const int s = w0 - 64 + r0;
            float4 v;
            v.x = rrow[(size_t)max(s + 0, 0) * Cd + cb + fc];
            v.y = rrow[(size_t)max(s + 1, 0) * Cd + cb + fc];
            v.z = rrow[(size_t)max(s + 2, 0) * Cd + cb + fc];
            v.w = rrow[(size_t)max(s + 3, 0) * Cd + cb + fc];
            *(float4*)&Rs[fc * SRP + r0] = v;
        }
        __syncthreads();

        // ---- compute 32 channels ----
#pragma unroll 1
        for (int g = 0; g < 4; g++) {
            const float* lgs = Ls + g * 8 * SLP + lb;
            const float* rgs = Rs + g * 8 * SRP + xb;
#pragma unroll
            for (int k = 0; k < 8; k++) {
                const float* lsrc = lgs + ro_l[k];
                const float* rsrc = rgs + ro_r[k];

                ull la[4];                         // {L[lb+2ii], L[lb+2ii+1]}
                *(ulonglong2*)&la[0] = *(const ulonglong2*)(lsrc);
                *(ulonglong2*)&la[2] = *(const ulonglong2*)(lsrc + 4);

                ull rr[12];                        // r[0..23] aligned pairs
#pragma unroll
                for (int m = 0; m < 6; m++)
                    *(ulonglong2*)&rr[2 * m] = *(const ulonglong2*)(rsrc + 4 * m);

                ull so[11];                        // {r[2q+1], r[2q+2]}
#pragma unroll
                for (int q = 0; q < 11; q++) so[q] = mid2(rr[q], rr[q + 1]);

#pragma unroll
                for (int ii = 0; ii < 4; ii++)
#pragma unroll
                    for (int j = 0; j < 16; j++) {
                        const int kk = 15 + 2 * ii - j;        // 0..21
                        const ull b = (kk & 1) ? so[kk >> 1] : rr[kk >> 1];
                        ffma2(p[ii][j], la[ii], b);
                    }
            }
        }
    }

    // ---- epilogue: unpack, scale, mask src<0, vector stores ----
    const float scale = 1.0f / 64.0f;
#pragma unroll
    for (int ii = 0; ii < 4; ii++) {
        float a0[16], a1[16];
#pragma unroll
        for (int j = 0; j < 16; j++) unpack2(p[ii][j], a0[j], a1[j]);
#pragma unroll
        for (int h = 0; h < 2; h++) {
            const float* acc = h ? a1 : a0;
            const int wg = w0 + lb + 2 * ii + h;           // global w
            float* op = out + ((size_t)bh * Wd + wg) * Dd + 16 * tx;
            float v[16];
#pragma unroll
            for (int j = 0; j < 16; j++) {
                const int src = wg - (16 * tx + j) - 1;
                v[j] = (src >= 0) ? acc[j] * scale : 0.0f;
            }
#pragma unroll
            for (int q = 0; q < 4; q++)
                *(float4*)(op + 4 * q) =
                    make_float4(v[4 * q], v[4 * q + 1], v[4 * q + 2], v[4 * q + 3]);
        }
    }
}

extern "C" void kernel_launch(void* const* d_in, const int* in_sizes, int n_in,
                              void* d_out, int out_size) {
    const float* left  = (const float*)d_in[0];
    const float* right = (const float*)d_in[1];
    float* outp = (float*)d_out;

    const int BH = in_sizes[0] / (Wd * Cd);
    dim3 grid(Wd / WT, BH, 1);
    cost_volume_kernel<<<grid, 64>>>(left, right, outp);
}

// round 5
// speedup vs baseline: 2.0287x; 2.0287x over previous
#include <cuda_runtime.h>

typedef unsigned int u32;

// CostVolume via banded tf32 GEMM on the legacy mma.sync (HMMA) path.
// Per (bh, 128-w tile): warp wid computes G[32,96] = L[32,64] . R[96,64]^T
// (rows 32*wid.., band cols s_local = 32*wid .. +95), then
// out[w, d] = G[w_local, w_local + 63 - d] / 64, masked where w-1-d < 0.

namespace {
constexpr int Wd = 512, Cd = 64, Dd = 64, WT = 128, BR = 192;
constexpr int P        = 40;              // smem pitch (words) per 32-ch phase
constexpr int LS_WORDS = 128 * P;         // 5120
constexpr int RS_WORDS = 192 * P;         // 7680
constexpr int SMEM_BYTES = (LS_WORDS + RS_WORDS) * 4;   // 51,200
constexpr int STG_P    = 68;              // staging pitch (words), 16B-aligned
}

__device__ __forceinline__ u32 f2tf32(float x) {
    u32 r;
    asm("cvt.rna.tf32.f32 %0, %1;" : "=r"(r) : "f"(x));
    return r;
}
__device__ __forceinline__ void mma_tf32(float* d, const u32* a, u32 b0, u32 b1) {
    asm("mma.sync.aligned.m16n8k8.row.col.f32.tf32.tf32.f32 "
        "{%0,%1,%2,%3}, {%4,%5,%6,%7}, {%8,%9}, {%0,%1,%2,%3};"
        : "+f"(d[0]), "+f"(d[1]), "+f"(d[2]), "+f"(d[3])
        : "r"(a[0]), "r"(a[1]), "r"(a[2]), "r"(a[3]), "r"(b0), "r"(b1));
}

__global__ __launch_bounds__(128, 3)
void cost_volume_mma_kernel(const float* __restrict__ left,
                            const float* __restrict__ right,
                            float* __restrict__ out) {
    extern __shared__ u32 sm[];
    u32* Ls = sm;                 // [w_local 0..127][c 0..31], pitch P
    u32* Rs = sm + LS_WORDS;      // [s_local 0..191][c 0..31], pitch P

    const int tid  = threadIdx.x;
    const int wid  = tid >> 5;
    const int lane = tid & 31;
    const int q    = lane >> 2;       // 0..7
    const int c    = lane & 3;        // 0..3
    const int w0   = blockIdx.x * WT;
    const int bh   = blockIdx.y;

    const float* lrow = left  + (size_t)bh * Wd * Cd;
    const float* rrow = right + (size_t)bh * Wd * Cd;

    float acc[2][12][4];
#pragma unroll
    for (int mt = 0; mt < 2; mt++)
#pragma unroll
        for (int nt = 0; nt < 12; nt++)
#pragma unroll
            for (int r = 0; r < 4; r++) acc[mt][nt][r] = 0.0f;

    for (int ph = 0; ph < 2; ph++) {
        const int cb = 32 * ph;
        if (ph) __syncthreads();

        // ---- fill (tf32-converted), coalesced 128B rows ----
#pragma unroll
        for (int i = 0; i < 8; i++) {
            const int idx = tid + 128 * i;       // 0..1023
            const int row = idx >> 3, c4 = idx & 7;
            const float4 v = *(const float4*)(lrow + (size_t)(w0 + row) * Cd + cb + 4 * c4);
            uint4 t = make_uint4(f2tf32(v.x), f2tf32(v.y), f2tf32(v.z), f2tf32(v.w));
            *(uint4*)&Ls[row * P + 4 * c4] = t;
        }
#pragma unroll
        for (int i = 0; i < 12; i++) {
            const int idx = tid + 128 * i;       // 0..1535
            const int row = idx >> 3, c4 = idx & 7;
            const int s = max(w0 - 64 + row, 0);     // clamped; masked later
            const float4 v = *(const float4*)(rrow + (size_t)s * Cd + cb + 4 * c4);
            uint4 t = make_uint4(f2tf32(v.x), f2tf32(v.y), f2tf32(v.z), f2tf32(v.w));
            *(uint4*)&Rs[row * P + 4 * c4] = t;
        }
        __syncthreads();

        // ---- compute: 4 K-steps of 8 (k-permuted fragments via v2 loads) ----
#pragma unroll
        for (int ks = 0; ks < 4; ks++) {
            const int kb = 8 * ks + 2 * c;      // permuted slot base
            u32 a[2][4];
#pragma unroll
            for (int mt = 0; mt < 2; mt++) {
                const u32* pa = &Ls[(32 * wid + 16 * mt + q) * P + kb];
                const uint2 lo = *(const uint2*)pa;
                const uint2 hi = *(const uint2*)(pa + 8 * P);
                a[mt][0] = lo.x; a[mt][2] = lo.y;   // slots k=c, k=c+4 (row q)
                a[mt][1] = hi.x; a[mt][3] = hi.y;   // same, row q+8
            }
#pragma unroll
            for (int nt = 0; nt < 12; nt++) {
                const uint2 bb = *(const uint2*)&Rs[(32 * wid + 8 * nt + q) * P + kb];
                mma_tf32(acc[0][nt], a[0], bb.x, bb.y);
                mma_tf32(acc[1][nt], a[1], bb.x, bb.y);
            }
        }
    }

    // ---- epilogue: diagonal extraction into smem staging ----
    __syncthreads();
    float* stage = (float*)sm;                    // [128][STG_P]
    const float scale = 1.0f / 64.0f;
#pragma unroll
    for (int mt = 0; mt < 2; mt++)
#pragma unroll
        for (int nt = 0; nt < 12; nt++)
#pragma unroll
            for (int r = 0; r < 4; r++) {
                const int d = 63 + 16 * mt - 8 * nt + q + 8 * (r >> 1) - 2 * c - (r & 1);
                if (d >= 0 && d < 64) {
                    const int w_l = 32 * wid + 16 * mt + 8 * (r >> 1) + q;
                    const int s_l = w_l + 63 - d;
                    const float val = (w0 + s_l >= 64) ? acc[mt][nt][r] * scale : 0.0f;
                    stage[w_l * STG_P + d] = val;
                }
            }
    __syncthreads();

    // ---- coalesced copy staging -> gmem ----
#pragma unroll
    for (int i = 0; i < 16; i++) {
        const int idx = tid + 128 * i;           // 0..2047
        const int row = idx >> 4, c4 = idx & 15;
        const float4 v = *(const float4*)(stage + row * STG_P + 4 * c4);
        *(float4*)(out + ((size_t)bh * Wd + w0 + row) * Dd + 4 * c4) = v;
    }
}

extern "C" void kernel_launch(void* const* d_in, const int* in_sizes, int n_in,
                              void* d_out, int out_size) {
    const float* left  = (const float*)d_in[0];
    const float* right = (const float*)d_in[1];
    float* outp = (float*)d_out;

    const int BH = in_sizes[0] / (Wd * Cd);

    cudaFuncSetAttribute(cost_volume_mma_kernel,
                         cudaFuncAttributeMaxDynamicSharedMemorySize, SMEM_BYTES);
    dim3 grid(Wd / WT, BH, 1);
    cost_volume_mma_kernel<<<grid, 128, SMEM_BYTES>>>(left, right, outp);
}

// round 6
// speedup vs baseline: 2.3336x; 1.1503x over previous
#include <cuda_runtime.h>

typedef unsigned int u32;

// CostVolume via banded tf32 GEMM (mma.sync m16n8k8).
// Block = (bh, 128-w tile), 256 threads / 8 warps.
// Warp wid: G[16,80] = L[rows 16wid..+15, 64] . R[rows 16wid..+79, 64]^T
// (R row r <-> src = w0-64+r), out[w,d] = G[w_l, w_l+63-d]/64, masked src<0.
// Two 32-channel phases; phase-1 globals prefetched into registers during
// phase-0 compute.

namespace {
constexpr int Wd = 512, Cd = 64, Dd = 64, WT = 128;
constexpr int P        = 40;              // smem pitch (words)
constexpr int LS_WORDS = 128 * P;         // 5120
constexpr int RS_WORDS = 192 * P;         // 7680
constexpr int SMEM_BYTES = (LS_WORDS + RS_WORDS) * 4;   // 51,200
constexpr int STG_P    = 68;              // staging pitch (words)
}

__device__ __forceinline__ u32 f2tf32(float x) {
    u32 r;
    asm("cvt.rna.tf32.f32 %0, %1;" : "=r"(r) : "f"(x));
    return r;
}
__device__ __forceinline__ void mma_tf32(float* d, const u32* a, u32 b0, u32 b1) {
    asm("mma.sync.aligned.m16n8k8.row.col.f32.tf32.tf32.f32 "
        "{%0,%1,%2,%3}, {%4,%5,%6,%7}, {%8,%9}, {%0,%1,%2,%3};"
        : "+f"(d[0]), "+f"(d[1]), "+f"(d[2]), "+f"(d[3])
        : "r"(a[0]), "r"(a[1]), "r"(a[2]), "r"(a[3]), "r"(b0), "r"(b1));
}

__global__ __launch_bounds__(256, 2)
void cost_volume_mma_kernel(const float* __restrict__ left,
                            const float* __restrict__ right,
                            float* __restrict__ out) {
    extern __shared__ u32 sm[];
    u32* Ls = sm;                 // [w_local 0..127][c 0..31], pitch P
    u32* Rs = sm + LS_WORDS;      // [s_local 0..191][c 0..31], pitch P

    const int tid  = threadIdx.x;
    const int wid  = tid >> 5;        // 0..7
    const int lane = tid & 31;
    const int q    = lane >> 2;       // 0..7
    const int c    = lane & 3;        // 0..3
    const int w0   = blockIdx.x * WT;
    const int bh   = blockIdx.y;

    const float* lrow = left  + (size_t)bh * Wd * Cd;
    const float* rrow = right + (size_t)bh * Wd * Cd;

    // fill indexing (fixed per thread)
    const int frowL0 = tid >> 3;              // L rows: frowL0 + 32*i
    const int fc4    = tid & 7;

    float acc[10][4];
#pragma unroll
    for (int nt = 0; nt < 10; nt++)
#pragma unroll
        for (int r = 0; r < 4; r++) acc[nt][r] = 0.0f;

    float4 lst[4], rst[6];

    // ---- prologue: load + store phase 0 ----
#pragma unroll
    for (int i = 0; i < 4; i++)
        lst[i] = *(const float4*)(lrow + (size_t)(w0 + frowL0 + 32 * i) * Cd + 4 * fc4);
#pragma unroll
    for (int i = 0; i < 6; i++) {
        const int s = max(w0 - 64 + frowL0 + 32 * i, 0);
        rst[i] = *(const float4*)(rrow + (size_t)s * Cd + 4 * fc4);
    }
#pragma unroll
    for (int i = 0; i < 4; i++) {
        uint4 t = make_uint4(f2tf32(lst[i].x), f2tf32(lst[i].y),
                             f2tf32(lst[i].z), f2tf32(lst[i].w));
        *(uint4*)&Ls[(frowL0 + 32 * i) * P + 4 * fc4] = t;
    }
#pragma unroll
    for (int i = 0; i < 6; i++) {
        uint4 t = make_uint4(f2tf32(rst[i].x), f2tf32(rst[i].y),
                             f2tf32(rst[i].z), f2tf32(rst[i].w));
        *(uint4*)&Rs[(frowL0 + 32 * i) * P + 4 * fc4] = t;
    }
    __syncthreads();

    // ---- issue phase-1 LDGs (consumed after phase-0 compute) ----
#pragma unroll
    for (int i = 0; i < 4; i++)
        lst[i] = *(const float4*)(lrow + (size_t)(w0 + frowL0 + 32 * i) * Cd + 32 + 4 * fc4);
#pragma unroll
    for (int i = 0; i < 6; i++) {
        const int s = max(w0 - 64 + frowL0 + 32 * i, 0);
        rst[i] = *(const float4*)(rrow + (size_t)s * Cd + 32 + 4 * fc4);
    }

    // ---- compute phase 0 ----
    const u32* la_base = &Ls[(16 * wid + q) * P];
    const u32* rb_base = &Rs[(16 * wid + q) * P];
#pragma unroll
    for (int ks = 0; ks < 4; ks++) {
        const int kb = 8 * ks + 2 * c;
        u32 a[4];
        {
            const uint2 lo = *(const uint2*)(la_base + kb);
            const uint2 hi = *(const uint2*)(la_base + 8 * P + kb);
            a[0] = lo.x; a[2] = lo.y; a[1] = hi.x; a[3] = hi.y;
        }
#pragma unroll
        for (int nt = 0; nt < 10; nt++) {
            const uint2 bb = *(const uint2*)(rb_base + (8 * nt) * P + kb);
            mma_tf32(acc[nt], a, bb.x, bb.y);
        }
    }
    __syncthreads();

    // ---- store phase 1 ----
#pragma unroll
    for (int i = 0; i < 4; i++) {
        uint4 t = make_uint4(f2tf32(lst[i].x), f2tf32(lst[i].y),
                             f2tf32(lst[i].z), f2tf32(lst[i].w));
        *(uint4*)&Ls[(frowL0 + 32 * i) * P + 4 * fc4] = t;
    }
#pragma unroll
    for (int i = 0; i < 6; i++) {
        uint4 t = make_uint4(f2tf32(rst[i].x), f2tf32(rst[i].y),
                             f2tf32(rst[i].z), f2tf32(rst[i].w));
        *(uint4*)&Rs[(frowL0 + 32 * i) * P + 4 * fc4] = t;
    }
    __syncthreads();

    // ---- compute phase 1 ----
#pragma unroll
    for (int ks = 0; ks < 4; ks++) {
        const int kb = 8 * ks + 2 * c;
        u32 a[4];
        {
            const uint2 lo = *(const uint2*)(la_base + kb);
            const uint2 hi = *(const uint2*)(la_base + 8 * P + kb);
            a[0] = lo.x; a[2] = lo.y; a[1] = hi.x; a[3] = hi.y;
        }
#pragma unroll
        for (int nt = 0; nt < 10; nt++) {
            const uint2 bb = *(const uint2*)(rb_base + (8 * nt) * P + kb);
            mma_tf32(acc[nt], a, bb.x, bb.y);
        }
    }

    // ---- epilogue: diagonal extraction into smem staging ----
    __syncthreads();
    float* stage = (float*)sm;                    // [128][STG_P]
    const float scale = 1.0f / 64.0f;
#pragma unroll
    for (int nt = 0; nt < 10; nt++)
#pragma unroll
        for (int r = 0; r < 4; r++) {
            const int d = 63 + q + 8 * (r >> 1) - 8 * nt - 2 * c - (r & 1);
            if (d >= 0 && d < 64) {
                const int w_l = 16 * wid + q + 8 * (r >> 1);
                const int s_l = w_l + 63 - d;
                const float val = (w0 + s_l >= 64) ? acc[nt][r] * scale : 0.0f;
                stage[w_l * STG_P + d] = val;
            }
        }
    __syncthreads();

    // ---- coalesced copy staging -> gmem ----
#pragma unroll
    for (int i = 0; i < 8; i++) {
        const int idx = tid + 256 * i;           // 0..2047
        const int row = idx >> 4, c4 = idx & 15;
        const float4 v = *(const float4*)(stage + row * STG_P + 4 * c4);
        *(float4*)(out + ((size_t)bh * Wd + w0 + row) * Dd + 4 * c4) = v;
    }
}

extern "C" void kernel_launch(void* const* d_in, const int* in_sizes, int n_in,
                              void* d_out, int out_size) {
    const float* left  = (const float*)d_in[0];
    const float* right = (const float*)d_in[1];
    float* outp = (float*)d_out;

    const int BH = in_sizes[0] / (Wd * Cd);

    cudaFuncSetAttribute(cost_volume_mma_kernel,
                         cudaFuncAttributeMaxDynamicSharedMemorySize, SMEM_BYTES);
    dim3 grid(Wd / WT, BH, 1);
    cost_volume_mma_kernel<<<grid, 256, SMEM_BYTES>>>(left, right, outp);
}